// round 3
// baseline (speedup 1.0000x reference)
#include <cuda_runtime.h>
#include <math.h>

#define BB 2
#define NN 2048
#define DM 512
#define NH 8
#define HD 64
#define TOPK 64
#define BH (BB*NH)       // 16
#define M_TOT (BB*NN)    // 4096
#define SCALEF 0.125f

// ---------------- scratch (static __device__ per allocation rules) ----------
__device__ float g_Qh[BH*NN*HD];            // [bh][n][d]  (Q pre-scaled by 1/8)
__device__ float g_Kh[BH*NN*HD];
__device__ float g_Vh[BH*NN*HD];
__device__ float g_S[(size_t)BH*NN*NN];     // raw scores 256MB
__device__ float g_H[M_TOT*DM];             // merged-head attn output

// ---------------------------------------------------------------------------
// 128x128-tile fp32 GEMM, 8x8 micro-tile, BK=16, 256 threads, double-buffered.
// C[m][o] = sum_k X[m][k] * W[o][k] + bias[o]
// mode 0: fused QKV (blockIdx.x: which=bx>>2, o0=(bx&3)*128), head-split out,
//         Q scaled by SCALEF.   mode 1: out-projection from g_H.
// ---------------------------------------------------------------------------
__global__ __launch_bounds__(256)
void gemm128(const float* __restrict__ X0, const float* __restrict__ X1,
             const float* __restrict__ X2,
             const float* __restrict__ W0, const float* __restrict__ W1,
             const float* __restrict__ W2,
             const float* __restrict__ b0, const float* __restrict__ b1,
             const float* __restrict__ b2,
             float* __restrict__ outp, int mode)
{
    __shared__ float XsT[2][16][132];
    __shared__ float WsT[2][16][132];

    const int tid = threadIdx.x;
    const int tx = tid & 15, ty = tid >> 4;
    const int m0 = blockIdx.y * 128;

    int which = 0, o0 = 0;
    const float *X, *W, *bias;
    if (mode == 0) {
        which = blockIdx.x >> 2;
        o0 = (blockIdx.x & 3) * 128;
        X    = (which == 0) ? X0 : (which == 1) ? X1 : X2;
        W    = (which == 0) ? W0 : (which == 1) ? W1 : W2;
        bias = (which == 0) ? b0 : (which == 1) ? b1 : b2;
    } else {
        o0 = blockIdx.x * 128;
        X = g_H; W = W0; bias = b0;
    }

    const int lr  = tid >> 2;          // 0..63  (row pair-index base)
    const int lc4 = (tid & 3) * 4;     // 0,4,8,12

    float acc[8][8];
#pragma unroll
    for (int i = 0; i < 8; i++)
#pragma unroll
        for (int j = 0; j < 8; j++) acc[i][j] = 0.f;

    float4 xr[2], wr[2];
    // preload chunk 0 into regs, stage to buffer 0
#pragma unroll
    for (int j = 0; j < 2; j++) {
        int r = lr + j * 64;
        xr[j] = *(const float4*)&X[(size_t)(m0 + r) * DM + lc4];
        wr[j] = *(const float4*)&W[(size_t)(o0 + r) * DM + lc4];
    }
#pragma unroll
    for (int j = 0; j < 2; j++) {
        int r = lr + j * 64;
        XsT[0][lc4 + 0][r] = xr[j].x; XsT[0][lc4 + 1][r] = xr[j].y;
        XsT[0][lc4 + 2][r] = xr[j].z; XsT[0][lc4 + 3][r] = xr[j].w;
        WsT[0][lc4 + 0][r] = wr[j].x; WsT[0][lc4 + 1][r] = wr[j].y;
        WsT[0][lc4 + 2][r] = wr[j].z; WsT[0][lc4 + 3][r] = wr[j].w;
    }
    __syncthreads();

    int p = 0;
    for (int k0 = 0; k0 < DM; k0 += 16) {
        const int kn = k0 + 16;
        if (kn < DM) {
#pragma unroll
            for (int j = 0; j < 2; j++) {
                int r = lr + j * 64;
                xr[j] = *(const float4*)&X[(size_t)(m0 + r) * DM + kn + lc4];
                wr[j] = *(const float4*)&W[(size_t)(o0 + r) * DM + kn + lc4];
            }
        }
#pragma unroll
        for (int kk = 0; kk < 16; kk++) {
            float4 a0 = *(const float4*)&XsT[p][kk][ty * 4];
            float4 a1 = *(const float4*)&XsT[p][kk][64 + ty * 4];
            float4 bv0 = *(const float4*)&WsT[p][kk][tx * 4];
            float4 bv1 = *(const float4*)&WsT[p][kk][64 + tx * 4];
            float a[8] = {a0.x, a0.y, a0.z, a0.w, a1.x, a1.y, a1.z, a1.w};
            float b[8] = {bv0.x, bv0.y, bv0.z, bv0.w, bv1.x, bv1.y, bv1.z, bv1.w};
#pragma unroll
            for (int i = 0; i < 8; i++)
#pragma unroll
                for (int j = 0; j < 8; j++) acc[i][j] += a[i] * b[j];
        }
        if (kn < DM) {
            int pn = p ^ 1;
#pragma unroll
            for (int j = 0; j < 2; j++) {
                int r = lr + j * 64;
                XsT[pn][lc4 + 0][r] = xr[j].x; XsT[pn][lc4 + 1][r] = xr[j].y;
                XsT[pn][lc4 + 2][r] = xr[j].z; XsT[pn][lc4 + 3][r] = xr[j].w;
                WsT[pn][lc4 + 0][r] = wr[j].x; WsT[pn][lc4 + 1][r] = wr[j].y;
                WsT[pn][lc4 + 2][r] = wr[j].z; WsT[pn][lc4 + 3][r] = wr[j].w;
            }
        }
        __syncthreads();
        p ^= 1;
    }

    const float sc = (mode == 0 && which == 0) ? SCALEF : 1.f;
#pragma unroll
    for (int i = 0; i < 8; i++) {
        int m = m0 + ((i < 4) ? ty * 4 + i : 64 + ty * 4 + (i - 4));
#pragma unroll
        for (int jg = 0; jg < 2; jg++) {
            int oc = o0 + ((jg == 0) ? tx * 4 : 64 + tx * 4);
            float4 v;
            v.x = (acc[i][jg * 4 + 0] + bias[oc + 0]) * sc;
            v.y = (acc[i][jg * 4 + 1] + bias[oc + 1]) * sc;
            v.z = (acc[i][jg * 4 + 2] + bias[oc + 2]) * sc;
            v.w = (acc[i][jg * 4 + 3] + bias[oc + 3]) * sc;
            if (mode == 0) {
                int b = m >> 11, n = m & (NN - 1);
                int h = oc >> 6, d = oc & 63;
                float* dst = (which == 0) ? g_Qh : (which == 1) ? g_Kh : g_Vh;
                *(float4*)&dst[(size_t)((b * NH + h) * NN + n) * HD + d] = v;
            } else {
                *(float4*)&outp[(size_t)m * DM + oc] = v;
            }
        }
    }
}

// ---------------------------------------------------------------------------
// Scores: per (b,h), S = Qh(2048x64) @ Kh^T (Q pre-scaled). 128x128 tiles,
// full K-dim (=64) resident: ONE sync, 64 straight k-steps. Dynamic smem.
// grid (16,16,16), 256 threads, 67.6KB smem.
// ---------------------------------------------------------------------------
__global__ __launch_bounds__(256)
void scores_kernel()
{
    extern __shared__ float smem_sc[];
    float (*QsT)[132] = (float(*)[132])smem_sc;              // [64][132]
    float (*KsT)[132] = (float(*)[132])(smem_sc + 64 * 132);

    const int bh = blockIdx.z;
    const int kx = blockIdx.x * 128;
    const int qy = blockIdx.y * 128;
    const int tid = threadIdx.x;
    const int tx = tid & 15, ty = tid >> 4;

#pragma unroll
    for (int j = 0; j < 8; j++) {
        int i = tid + j * 256;              // 0..2047 : 128 rows x 16 float4
        int r = i >> 4, c4 = (i & 15) * 4;
        float4 qv = *(const float4*)&g_Qh[((size_t)bh * NN + qy + r) * HD + c4];
        QsT[c4 + 0][r] = qv.x; QsT[c4 + 1][r] = qv.y;
        QsT[c4 + 2][r] = qv.z; QsT[c4 + 3][r] = qv.w;
        float4 kv = *(const float4*)&g_Kh[((size_t)bh * NN + kx + r) * HD + c4];
        KsT[c4 + 0][r] = kv.x; KsT[c4 + 1][r] = kv.y;
        KsT[c4 + 2][r] = kv.z; KsT[c4 + 3][r] = kv.w;
    }
    __syncthreads();

    float acc[8][8];
#pragma unroll
    for (int i = 0; i < 8; i++)
#pragma unroll
        for (int j = 0; j < 8; j++) acc[i][j] = 0.f;

#pragma unroll 8
    for (int d = 0; d < 64; d++) {
        float4 a0 = *(const float4*)&QsT[d][ty * 4];
        float4 a1 = *(const float4*)&QsT[d][64 + ty * 4];
        float4 bv0 = *(const float4*)&KsT[d][tx * 4];
        float4 bv1 = *(const float4*)&KsT[d][64 + tx * 4];
        float a[8] = {a0.x, a0.y, a0.z, a0.w, a1.x, a1.y, a1.z, a1.w};
        float b[8] = {bv0.x, bv0.y, bv0.z, bv0.w, bv1.x, bv1.y, bv1.z, bv1.w};
#pragma unroll
        for (int i = 0; i < 8; i++)
#pragma unroll
            for (int j = 0; j < 8; j++) acc[i][j] += a[i] * b[j];
    }

#pragma unroll
    for (int i = 0; i < 8; i++) {
        int row = qy + ((i < 4) ? ty * 4 + i : 64 + ty * 4 + (i - 4));
#pragma unroll
        for (int jg = 0; jg < 2; jg++) {
            int col = kx + ((jg == 0) ? tx * 4 : 64 + tx * 4);
            float4 v = make_float4(acc[i][jg * 4 + 0], acc[i][jg * 4 + 1],
                                   acc[i][jg * 4 + 2], acc[i][jg * 4 + 3]);
            __stcs((float4*)&g_S[((size_t)bh * NN + row) * NN + col], v);
        }
    }
}

// ---------------------------------------------------------------------------
// Per-row: exact top-64 (MSB radix select, warp-aggregated pass-0 histogram),
// softmax, attn row write (float4 streaming), AV.  grid 32768 x 256.
// Thread t owns columns t*8 .. t*8+7 (two float4).
// ---------------------------------------------------------------------------
__global__ __launch_bounds__(256)
void topk_av(float* __restrict__ attn, int write_attn)
{
    const int row = blockIdx.x;           // bh*N + q
    const int bh  = row >> 11;
    const int q   = row & (NN - 1);
    const int tid = threadIdx.x;
    const int lane = tid & 31, wid = tid >> 5;

    __shared__ int hist[256];
    __shared__ int wsum[8];
    __shared__ int wsuf[8];
    __shared__ float red[8];
    __shared__ int   sidx[128];
    __shared__ float sw[128];
    __shared__ unsigned sh_prefix;
    __shared__ int sh_kk;
    __shared__ int sh_cnt;
    __shared__ float sh_rmax, sh_invz;

    // ---- load 8 scores per thread: two float4 (cols tid*8 .. tid*8+7) ----
    const float4* Srow = (const float4*)&g_S[(size_t)row * NN];
    float4 v0 = __ldcs(&Srow[tid * 2]);
    float4 v1 = __ldcs(&Srow[tid * 2 + 1]);
    float sreg[8] = {v0.x, v0.y, v0.z, v0.w, v1.x, v1.y, v1.z, v1.w};
    unsigned keys[8];
#pragma unroll
    for (int e = 0; e < 8; e++) {
        unsigned u = __float_as_uint(sreg[e]);
        keys[e] = (u & 0x80000000u) ? ~u : (u | 0x80000000u);
    }

    // ---- radix select: exact 64th-largest key, 4 x 8-bit MSB passes ----
    unsigned prefix = 0;
    int kk = TOPK;
    for (int pass = 0; pass < 4; pass++) {
        hist[tid] = 0;
        __syncthreads();
        const int shift = 24 - 8 * pass;
        if (pass == 0) {
            // all elements participate: warp-aggregate to kill contention
#pragma unroll
            for (int e = 0; e < 8; e++) {
                unsigned bin = keys[e] >> 24;
                unsigned mm = __match_any_sync(0xffffffffu, bin);
                if ((int)(__ffs(mm) - 1) == lane)
                    atomicAdd(&hist[bin], __popc(mm));
            }
        } else {
#pragma unroll
            for (int e = 0; e < 8; e++) {
                unsigned k = keys[e];
                unsigned hi = (k >> (31 - 8 * pass)) >> 1;   // top 8*pass bits
                if (hi == prefix) atomicAdd(&hist[(k >> shift) & 255u], 1);
            }
        }
        __syncthreads();
        int v = hist[tid];
        int s = v;                          // inclusive suffix sum within warp
#pragma unroll
        for (int off = 1; off < 32; off <<= 1) {
            int t = __shfl_down_sync(0xffffffffu, s, off);
            if (lane + off < 32) s += t;
        }
        if (lane == 0) wsum[wid] = s;       // warp total
        __syncthreads();
        if (tid < 8) {
            int t = 0;
            for (int j = tid + 1; j < 8; j++) t += wsum[j];
            wsuf[tid] = t;
        }
        __syncthreads();
        int S = s + wsuf[wid];              // count of elems with bin >= tid
        if (S >= kk && S - v < kk && v > 0) {
            sh_prefix = (prefix << 8) | (unsigned)tid;
            sh_kk = kk - (S - v);
        }
        __syncthreads();
        prefix = sh_prefix;
        kk = sh_kk;
        __syncthreads();
    }
    const unsigned kth = prefix;            // exact 64th-largest key

    // ---- row max ----
    float lmax = -3.4e38f;
#pragma unroll
    for (int e = 0; e < 8; e++) lmax = fmaxf(lmax, sreg[e]);
#pragma unroll
    for (int off = 16; off > 0; off >>= 1)
        lmax = fmaxf(lmax, __shfl_xor_sync(0xffffffffu, lmax, off));
    if (lane == 0) red[wid] = lmax;
    __syncthreads();
    if (tid == 0) {
        float m = red[0];
        for (int j = 1; j < 8; j++) m = fmaxf(m, red[j]);
        sh_rmax = m;
        sh_cnt = 0;
    }
    __syncthreads();
    const float rmax = sh_rmax;

    // ---- sum of exp over selected ----
    float lsum = 0.f;
#pragma unroll
    for (int e = 0; e < 8; e++)
        if (keys[e] >= kth) lsum += __expf(sreg[e] - rmax);
#pragma unroll
    for (int off = 16; off > 0; off >>= 1)
        lsum += __shfl_xor_sync(0xffffffffu, lsum, off);
    if (lane == 0) red[wid] = lsum;
    __syncthreads();
    if (tid == 0) {
        float z = 0.f;
        for (int j = 0; j < 8; j++) z += red[j];
        sh_invz = 1.f / z;
    }
    __syncthreads();
    const float inv_z = sh_invz;

    // ---- weights: write attn row (2x float4), gather selected (idx, w) ----
    float w[8];
#pragma unroll
    for (int e = 0; e < 8; e++) {
        bool sel = (keys[e] >= kth);
        w[e] = sel ? __expf(sreg[e] - rmax) * inv_z : 0.f;
        if (sel) {
            int p = atomicAdd(&sh_cnt, 1);
            if (p < 128) { sidx[p] = tid * 8 + e; sw[p] = w[e]; }
        }
    }
    if (write_attn) {
        float4* Arow = (float4*)&attn[(size_t)row * NN];
        __stcs(&Arow[tid * 2],     make_float4(w[0], w[1], w[2], w[3]));
        __stcs(&Arow[tid * 2 + 1], make_float4(w[4], w[5], w[6], w[7]));
    }
    __syncthreads();
    int cnt = sh_cnt; if (cnt > 128) cnt = 128;

    // ---- AV: out[d] = sum_j w_j * V[bh][idx_j][d] ----
    __shared__ float pacc[256];
    const int d = tid & 63;
    const int part = tid >> 6;
    float acc = 0.f;
    for (int j = part; j < cnt; j += 4)
        acc += sw[j] * g_Vh[(size_t)(bh * NN + sidx[j]) * HD + d];
    pacc[tid] = acc;
    __syncthreads();
    if (tid < 64) {
        float o = pacc[tid] + pacc[64 + tid] + pacc[128 + tid] + pacc[192 + tid];
        int b = bh >> 3, h = bh & 7;
        g_H[(size_t)(b * NN + q) * DM + h * HD + tid] = o;
    }
}

// ---------------------------------------------------------------------------
extern "C" void kernel_launch(void* const* d_in, const int* in_sizes, int n_in,
                              void* d_out, int out_size)
{
    const float* q  = (const float*)d_in[0];
    const float* k  = (const float*)d_in[1];
    const float* v  = (const float*)d_in[2];
    const float* wq = (const float*)d_in[3];
    const float* bq = (const float*)d_in[4];
    const float* wk = (const float*)d_in[5];
    const float* bk = (const float*)d_in[6];
    const float* wv = (const float*)d_in[7];
    const float* bv = (const float*)d_in[8];
    const float* wo = (const float*)d_in[9];
    const float* bo = (const float*)d_in[10];

    float* out = (float*)d_out;
    const long long OUT_ELEMS  = (long long)M_TOT * DM;        // 2,097,152
    const long long ATTN_ELEMS = (long long)BH * NN * NN;      // 67,108,864

    int write_attn = 0, write_out = 1;
    float* attn_ptr = nullptr;
    if ((long long)out_size >= OUT_ELEMS + ATTN_ELEMS) {
        write_attn = 1; attn_ptr = out + OUT_ELEMS;
    } else if ((long long)out_size == ATTN_ELEMS) {
        write_attn = 1; attn_ptr = out; write_out = 0;
    }

    // opt-in >48KB dynamic smem for scores (idempotent; no allocation)
    const int SC_SMEM = 2 * 64 * 132 * 4;   // 67584 bytes
    cudaFuncSetAttribute(scores_kernel,
                         cudaFuncAttributeMaxDynamicSharedMemorySize, SC_SMEM);

    gemm128<<<dim3(12, M_TOT / 128), 256>>>(q, k, v, wq, wk, wv, bq, bk, bv,
                                            nullptr, 0);

    scores_kernel<<<dim3(NN / 128, NN / 128, BH), 256, SC_SMEM>>>();

    topk_av<<<BH * NN, 256>>>(attn_ptr, write_attn);

    if (write_out)
        gemm128<<<dim3(DM / 128, M_TOT / 128), 256>>>(nullptr, nullptr, nullptr,
                                                      wo, nullptr, nullptr,
                                                      bo, nullptr, nullptr,
                                                      out, 1);
}